// round 9
// baseline (speedup 1.0000x reference)
#include <cuda_runtime.h>
#include <cuda_fp16.h>
#include <math.h>

#define NB 4
#define NT 1024
#define CM 256
#define NH 8
#define DHD 32
#define MTOT (NB*NT)   // 4096
#define NTSQ (NT*NT)

#define QSCALE (0.17677669529663687f * 1.4426950408889634f)
#define LOG2E  1.4426950408889634f

// ---- scratch (device globals) ----
__device__ float g_qkvT[(size_t)4*CM*MTOT];   // q tf32*QSCALE, k tf32, g fp32
__device__ __half g_vh[(size_t)CM*MTOT];      // v fp16: [(d*8+h)][m]
__device__ __half g_pbh[(size_t)NH*NT*NT];    // [h][i*1024+j], * log2e, fp16
__device__ float g_att[(size_t)MTOT*CM];      // [m][h*32+d]  tf32-bit floats

__device__ __forceinline__ unsigned f2tf(float x) {
    unsigned r; asm("cvt.rna.tf32.f32 %0, %1;" : "=r"(r) : "f"(x)); return r;
}
__device__ __forceinline__ unsigned fu(float x) { return __float_as_uint(x); }
__device__ __forceinline__ float ex2(float x) {
    float r; asm("ex2.approx.ftz.f32 %0, %1;" : "=f"(r) : "f"(x)); return r;
}
__device__ __forceinline__ void mma8(float* d, unsigned a0, unsigned a1,
                                     unsigned a2, unsigned a3,
                                     unsigned b0, unsigned b1) {
    asm("mma.sync.aligned.m16n8k8.row.col.f32.tf32.tf32.f32 "
        "{%0,%1,%2,%3}, {%4,%5,%6,%7}, {%8,%9}, {%0,%1,%2,%3};"
        : "+f"(d[0]), "+f"(d[1]), "+f"(d[2]), "+f"(d[3])
        : "r"(a0), "r"(a1), "r"(a2), "r"(a3), "r"(b0), "r"(b1));
}
__device__ __forceinline__ void mma16h(float* d, unsigned a0, unsigned a1,
                                       unsigned a2, unsigned a3,
                                       unsigned b0, unsigned b1) {
    asm("mma.sync.aligned.m16n8k16.row.col.f32.f16.f16.f32 "
        "{%0,%1,%2,%3}, {%4,%5,%6,%7}, {%8,%9}, {%0,%1,%2,%3};"
        : "+f"(d[0]), "+f"(d[1]), "+f"(d[2]), "+f"(d[3])
        : "r"(a0), "r"(a1), "r"(a2), "r"(a3), "r"(b0), "r"(b1));
}
__device__ __forceinline__ void cpa16(void* dst, const void* src) {
    unsigned s = (unsigned)__cvta_generic_to_shared(dst);
    asm volatile("cp.async.cg.shared.global [%0], [%1], 16;" :: "r"(s), "l"(src));
}
#define CP_COMMIT asm volatile("cp.async.commit_group;")
#define CP_WAIT0  asm volatile("cp.async.wait_group 0;")
#define CP_WAIT1  asm volatile("cp.async.wait_group 1;")

#define BIAS_BLOCKS 8192
#define FUSED_SMEM 67584
#define ATTN_SMEM  36864   // Qs 9216 + K dbuf 18432 + V dbuf 9216

// ============================================================
// K1 fused: blocks [0,8192) -> pair-bias ; blocks [8192,8704) -> qkv GEMM
// (qkv at the tail so the DRAM stream starts immediately)
// ============================================================
__global__ void __launch_bounds__(256) fused1_kernel(const float* __restrict__ x,
                                                     const float* __restrict__ Wqkv,
                                                     const float* __restrict__ bias_rep,
                                                     const float* __restrict__ Wb,
                                                     const float* __restrict__ bb) {
    extern __shared__ __align__(16) unsigned char smem_raw[];
    const int tid = threadIdx.x;
    const int warp = tid >> 5, lane = tid & 31;
    const int g = lane >> 2, tig = lane & 3;

    if (blockIdx.x >= BIAS_BLOCKS) {
        // ---------------- qkv role ----------------
        float* As = (float*)smem_raw;              // [128][36]
        float* Bs = As + 128 * 36;                 // [32][72]
        float* Ts = (float*)smem_raw;              // epilogue [64][132]
        const int qid = (int)blockIdx.x - BIAS_BLOCKS;
        const int wm = warp >> 1, wn = warp & 1;
        const int m0 = (qid & 31) * 128;
        const int n0 = (qid >> 5) * 64;

        float acc[2][4][4];
#pragma unroll
        for (int i = 0; i < 2; i++)
#pragma unroll
            for (int j = 0; j < 4; j++)
#pragma unroll
                for (int c = 0; c < 4; c++) acc[i][j][c] = 0.f;

        for (int k0 = 0; k0 < CM; k0 += 32) {
            __syncthreads();
            {
                int row = tid >> 1, half = tid & 1;
#pragma unroll
                for (int q = 0; q < 4; q++)
                    cpa16(As + row * 36 + half * 16 + q * 4,
                          x + (size_t)(m0 + row) * CM + k0 + half * 16 + q * 4);
            }
            {
#pragma unroll
                for (int p = 0; p < 2; p++) {
                    int row = (tid >> 4) + p * 16, c4 = (tid & 15) * 4;
                    cpa16(Bs + row * 72 + c4,
                          Wqkv + (size_t)(k0 + row) * 1024 + n0 + c4);
                }
            }
            CP_COMMIT; CP_WAIT0;
            __syncthreads();
#pragma unroll
            for (int kc = 0; kc < 4; kc++) {
                unsigned a[2][4];
#pragma unroll
                for (int mt = 0; mt < 2; mt++) {
                    int r = wm * 32 + mt * 16;
                    a[mt][0] = f2tf(As[(r + g) * 36 + kc * 8 + tig]);
                    a[mt][1] = f2tf(As[(r + g + 8) * 36 + kc * 8 + tig]);
                    a[mt][2] = f2tf(As[(r + g) * 36 + kc * 8 + tig + 4]);
                    a[mt][3] = f2tf(As[(r + g + 8) * 36 + kc * 8 + tig + 4]);
                }
#pragma unroll
                for (int nt = 0; nt < 4; nt++) {
                    int c = wn * 32 + nt * 8;
                    unsigned b0 = f2tf(Bs[(kc * 8 + tig) * 72 + c + g]);
                    unsigned b1 = f2tf(Bs[(kc * 8 + tig + 4) * 72 + c + g]);
                    mma8(acc[0][nt], a[0][0], a[0][1], a[0][2], a[0][3], b0, b1);
                    mma8(acc[1][nt], a[1][0], a[1][1], a[1][2], a[1][3], b0, b1);
                }
            }
        }
        __syncthreads();
#pragma unroll
        for (int mt = 0; mt < 2; mt++) {
            int r = wm * 32 + mt * 16 + g;
#pragma unroll
            for (int nt = 0; nt < 4; nt++) {
                int c = wn * 32 + nt * 8 + 2 * tig;
                Ts[c * 132 + r]           = acc[mt][nt][0];
                Ts[(c + 1) * 132 + r]     = acc[mt][nt][1];
                Ts[c * 132 + r + 8]       = acc[mt][nt][2];
                Ts[(c + 1) * 132 + r + 8] = acc[mt][nt][3];
            }
        }
        __syncthreads();
        {
            int col = tid >> 2, q = tid & 3;
            int n = n0 + col;
            int d = n >> 5, rr = n & 31;
            int kk = rr >> 3, h = rr & 7;
            const float* srcT = Ts + col * 132 + q * 32;
            if (kk == 2) {
                __half* dst = g_vh + (size_t)(d * 8 + h) * MTOT + m0 + q * 32;
#pragma unroll
                for (int i = 0; i < 4; i++) {
                    float4 v0 = *(const float4*)(srcT + i * 8);
                    float4 v1 = *(const float4*)(srcT + i * 8 + 4);
                    __half2 h0 = __floats2half2_rn(v0.x, v0.y);
                    __half2 h1 = __floats2half2_rn(v0.z, v0.w);
                    __half2 h2 = __floats2half2_rn(v1.x, v1.y);
                    __half2 h3 = __floats2half2_rn(v1.z, v1.w);
                    uint4 o = make_uint4(*(unsigned*)&h0, *(unsigned*)&h1,
                                         *(unsigned*)&h2, *(unsigned*)&h3);
                    *(uint4*)(dst + i * 8) = o;
                }
            } else {
                float* dst = g_qkvT + (size_t)n * MTOT + m0 + q * 32;
                if (kk == 3) {
#pragma unroll
                    for (int i = 0; i < 8; i++)
                        *(float4*)(dst + i * 4) = *(const float4*)(srcT + i * 4);
                } else {
                    float sc = (kk == 0) ? QSCALE : 1.0f;
#pragma unroll
                    for (int i = 0; i < 8; i++) {
                        float4 v = *(const float4*)(srcT + i * 4);
                        float4 o;
                        o.x = __uint_as_float(f2tf(v.x * sc));
                        o.y = __uint_as_float(f2tf(v.y * sc));
                        o.z = __uint_as_float(f2tf(v.z * sc));
                        o.w = __uint_as_float(f2tf(v.w * sc));
                        *(float4*)(dst + i * 4) = o;
                    }
                }
            }
        }
    } else {
        // ---------------- bias role: per-warp pipelined ----------------
        float* As = (float*)smem_raw + warp * (16 * 132);
        const int bid = (int)blockIdx.x;            // 0..8191
        const int bi = bid >> 3;
        const int j0 = (bid & 7) * 128 + warp * 16;

        unsigned wb0[16], wb1[16];
#pragma unroll
        for (int kc = 0; kc < 16; kc++) {
            wb0[kc] = f2tf(__ldg(&Wb[(kc * 8 + tig) * 8 + g]));
            wb1[kc] = f2tf(__ldg(&Wb[(kc * 8 + tig + 4) * 8 + g]));
        }
        float bbv0 = __ldg(&bb[2 * tig]);
        float bbv1 = __ldg(&bb[2 * tig + 1]);

        const float* src = bias_rep + ((size_t)bi * NT + j0) * 128;
#pragma unroll
        for (int p = 0; p < 8; p++) {
            int idx = lane + p * 32;
            int row = idx >> 4, c4 = (idx & 15) * 4;
            cpa16(As + row * 132 + c4, src + (size_t)row * 128 + c4);
        }
        CP_COMMIT;
#pragma unroll
        for (int p = 0; p < 8; p++) {
            int idx = lane + p * 32;
            int row = idx >> 4, c4 = (idx & 15) * 4 + 64;
            cpa16(As + row * 132 + c4, src + (size_t)row * 128 + c4);
        }
        CP_COMMIT;

        float dd[4] = {0.f, 0.f, 0.f, 0.f};
        CP_WAIT1;  __syncwarp();
#pragma unroll
        for (int kc = 0; kc < 8; kc++) {
            unsigned a0 = f2tf(As[g * 132 + kc * 8 + tig]);
            unsigned a1 = f2tf(As[(g + 8) * 132 + kc * 8 + tig]);
            unsigned a2 = f2tf(As[g * 132 + kc * 8 + tig + 4]);
            unsigned a3 = f2tf(As[(g + 8) * 132 + kc * 8 + tig + 4]);
            mma8(dd, a0, a1, a2, a3, wb0[kc], wb1[kc]);
        }
        CP_WAIT0;  __syncwarp();
#pragma unroll
        for (int kc = 8; kc < 16; kc++) {
            unsigned a0 = f2tf(As[g * 132 + kc * 8 + tig]);
            unsigned a1 = f2tf(As[(g + 8) * 132 + kc * 8 + tig]);
            unsigned a2 = f2tf(As[g * 132 + kc * 8 + tig + 4]);
            unsigned a3 = f2tf(As[(g + 8) * 132 + kc * 8 + tig + 4]);
            mma8(dd, a0, a1, a2, a3, wb0[kc], wb1[kc]);
        }
        size_t m = (size_t)bi * NT + j0 + g;
        g_pbh[(size_t)(2 * tig) * NTSQ     + m]     = __float2half((dd[0] + bbv0) * LOG2E);
        g_pbh[(size_t)(2 * tig + 1) * NTSQ + m]     = __float2half((dd[1] + bbv1) * LOG2E);
        g_pbh[(size_t)(2 * tig) * NTSQ     + m + 8] = __float2half((dd[2] + bbv0) * LOG2E);
        g_pbh[(size_t)(2 * tig + 1) * NTSQ + m + 8] = __float2half((dd[3] + bbv1) * LOG2E);
    }
}

// ============================================================
// K3: flash attention; S: tf32 HMMA; PV: fp16 HMMA
// 128 thr = 4 warps; block = (b,h) x 64 q-rows; grid 32x16
// ============================================================
__global__ void __launch_bounds__(128, 6) attn_kernel() {
    extern __shared__ float asmem[];
    float* Qs = asmem;                        // [32][72] fp32
    float* Ksb0 = asmem + 2304;               // [32][72] fp32
    float* Ksb1 = asmem + 4608;
    __half* Vsb0 = (__half*)(asmem + 6912);   // [32][72] half
    __half* Vsb1 = (__half*)(asmem + 8064);

    const int bh = blockIdx.x;
    const int b = bh >> 3, h = bh & 7;
    const int i0 = blockIdx.y * 64;
    const int tid = threadIdx.x;
    const int w = tid >> 5, lane = tid & 31;
    const int g = lane >> 2, tig = lane & 3;

    // stage Q (once): [d][i]
#pragma unroll
    for (int r = 0; r < 4; r++) {
        int c = tid + r * 128;
        int d = c >> 4, c4 = (c & 15) * 4;
        cpa16(Qs + d * 72 + c4,
              g_qkvT + (size_t)(d * 32 + h) * MTOT + b * NT + i0 + c4);
    }
    // stage K/V tile 0
#pragma unroll
    for (int r = 0; r < 4; r++) {
        int c = tid + r * 128;
        int d = c >> 4, c4 = (c & 15) * 4;
        cpa16(Ksb0 + d * 72 + c4, g_qkvT + (size_t)(d * 32 + 8 + h) * MTOT + b * NT + c4);
    }
#pragma unroll
    for (int r = 0; r < 2; r++) {
        int c = tid + r * 128;
        int d = c >> 3, c8 = (c & 7) * 8;
        cpa16(Vsb0 + d * 72 + c8, g_vh + (size_t)(d * 8 + h) * MTOT + b * NT + c8);
    }
    CP_COMMIT;

    float oacc[4][4];
#pragma unroll
    for (int i = 0; i < 4; i++)
#pragma unroll
        for (int c = 0; c < 4; c++) oacc[i][c] = 0.f;
    float mrow0 = -1e30f, mrow1 = -1e30f, lsum0 = 0.f, lsum1 = 0.f;

    const __half* pb0 = g_pbh + (size_t)h * NTSQ + (size_t)(i0 + w * 16 + g) * NT;
    const __half* pb1 = pb0 + 8 * NT;

    for (int n = 0; n < 16; n++) {
        CP_WAIT0;
        __syncthreads();
        const float* Ks = (n & 1) ? Ksb1 : Ksb0;
        const __half* Vs = (n & 1) ? Vsb1 : Vsb0;
        if (n < 15) {
            float* Kd = (n & 1) ? Ksb0 : Ksb1;
            __half* Vd = (n & 1) ? Vsb0 : Vsb1;
            int jn = (n + 1) * 64;
#pragma unroll
            for (int r = 0; r < 4; r++) {
                int c = tid + r * 128;
                int d = c >> 4, c4 = (c & 15) * 4;
                cpa16(Kd + d * 72 + c4,
                      g_qkvT + (size_t)(d * 32 + 8 + h) * MTOT + b * NT + jn + c4);
            }
#pragma unroll
            for (int r = 0; r < 2; r++) {
                int c = tid + r * 128;
                int d = c >> 3, c8 = (c & 7) * 8;
                cpa16(Vd + d * 72 + c8,
                      g_vh + (size_t)(d * 8 + h) * MTOT + b * NT + jn + c8);
            }
            CP_COMMIT;
        }
        const int jt = n * 64;

        // prefetch pair bias
        __half2 hp0[8], hp1[8];
#pragma unroll
        for (int nt = 0; nt < 8; nt++) {
            hp0[nt] = *(const __half2*)(pb0 + jt + nt * 8 + 2 * tig);
            hp1[nt] = *(const __half2*)(pb1 + jt + nt * 8 + 2 * tig);
        }

        // S = Q K^T (tf32)
        float sa[8][4];
#pragma unroll
        for (int nt = 0; nt < 8; nt++)
#pragma unroll
            for (int c = 0; c < 4; c++) sa[nt][c] = 0.f;
#pragma unroll
        for (int kc = 0; kc < 4; kc++) {
            const float* qrow = Qs + (kc * 8 + tig) * 72 + w * 16 + g;
            unsigned a0 = fu(qrow[0]);
            unsigned a1 = fu(qrow[8]);
            unsigned a2 = fu(qrow[288]);
            unsigned a3 = fu(qrow[296]);
#pragma unroll
            for (int nt = 0; nt < 8; nt++) {
                unsigned b0 = fu(Ks[(kc * 8 + tig) * 72 + nt * 8 + g]);
                unsigned b1 = fu(Ks[(kc * 8 + tig + 4) * 72 + nt * 8 + g]);
                mma8(sa[nt], a0, a1, a2, a3, b0, b1);
            }
        }
        // + pair bias
#pragma unroll
        for (int nt = 0; nt < 8; nt++) {
            float2 p0 = __half22float2(hp0[nt]);
            float2 p1 = __half22float2(hp1[nt]);
            sa[nt][0] += p0.x; sa[nt][1] += p0.y;
            sa[nt][2] += p1.x; sa[nt][3] += p1.y;
        }
        // online softmax (exp2)
        float t0 = -1e30f, t1 = -1e30f;
#pragma unroll
        for (int nt = 0; nt < 8; nt++) {
            t0 = fmaxf(t0, fmaxf(sa[nt][0], sa[nt][1]));
            t1 = fmaxf(t1, fmaxf(sa[nt][2], sa[nt][3]));
        }
        t0 = fmaxf(t0, __shfl_xor_sync(0xffffffffu, t0, 1));
        t0 = fmaxf(t0, __shfl_xor_sync(0xffffffffu, t0, 2));
        t1 = fmaxf(t1, __shfl_xor_sync(0xffffffffu, t1, 1));
        t1 = fmaxf(t1, __shfl_xor_sync(0xffffffffu, t1, 2));
        float mn0 = fmaxf(mrow0, t0), mn1 = fmaxf(mrow1, t1);
        float corr0 = ex2(mrow0 - mn0), corr1 = ex2(mrow1 - mn1);
        mrow0 = mn0; mrow1 = mn1;
        float l0 = 0.f, l1 = 0.f;
#pragma unroll
        for (int nt = 0; nt < 8; nt++) {
            sa[nt][0] = ex2(sa[nt][0] - mn0); l0 += sa[nt][0];
            sa[nt][1] = ex2(sa[nt][1] - mn0); l0 += sa[nt][1];
            sa[nt][2] = ex2(sa[nt][2] - mn1); l1 += sa[nt][2];
            sa[nt][3] = ex2(sa[nt][3] - mn1); l1 += sa[nt][3];
        }
        l0 += __shfl_xor_sync(0xffffffffu, l0, 1);
        l0 += __shfl_xor_sync(0xffffffffu, l0, 2);
        l1 += __shfl_xor_sync(0xffffffffu, l1, 1);
        l1 += __shfl_xor_sync(0xffffffffu, l1, 2);
        lsum0 = lsum0 * corr0 + l0;
        lsum1 = lsum1 * corr1 + l1;
#pragma unroll
        for (int nt = 0; nt < 4; nt++) {
            oacc[nt][0] *= corr0; oacc[nt][1] *= corr0;
            oacc[nt][2] *= corr1; oacc[nt][3] *= corr1;
        }

        // O += P @ V (fp16)
#pragma unroll
        for (int kc = 0; kc < 4; kc++) {
            __half2 h0 = __floats2half2_rn(sa[2 * kc][0],     sa[2 * kc][1]);
            __half2 h1 = __floats2half2_rn(sa[2 * kc][2],     sa[2 * kc][3]);
            __half2 h2 = __floats2half2_rn(sa[2 * kc + 1][0], sa[2 * kc + 1][1]);
            __half2 h3 = __floats2half2_rn(sa[2 * kc + 1][2], sa[2 * kc + 1][3]);
            unsigned a0 = *(unsigned*)&h0, a1 = *(unsigned*)&h1;
            unsigned a2 = *(unsigned*)&h2, a3 = *(unsigned*)&h3;
#pragma unroll
            for (int nt = 0; nt < 4; nt++) {
                unsigned b0 = *(const unsigned*)&Vs[(nt * 8 + g) * 72 + kc * 16 + 2 * tig];
                unsigned b1 = *(const unsigned*)&Vs[(nt * 8 + g) * 72 + kc * 16 + 2 * tig + 8];
                mma16h(oacc[nt], a0, a1, a2, a3, b0, b1);
            }
        }
    }

    // epilogue
    float inv0 = 1.f / lsum0, inv1 = 1.f / lsum1;
    int tg0 = i0 + w * 16 + g, tg1 = tg0 + 8;
#pragma unroll
    for (int nt = 0; nt < 4; nt++) {
        int d = nt * 8 + 2 * tig;
        const float* gq0 = g_qkvT + (size_t)(d * 32 + 24 + h) * MTOT + b * NT;
        const float* gq1 = g_qkvT + (size_t)((d + 1) * 32 + 24 + h) * MTOT + b * NT;
        float gv00 = gq0[tg0], gv01 = gq1[tg0];
        float gv10 = gq0[tg1], gv11 = gq1[tg1];
        float2 o0, o1;
        o0.x = __uint_as_float(f2tf(oacc[nt][0] * inv0 * (1.f / (1.f + __expf(-gv00)))));
        o0.y = __uint_as_float(f2tf(oacc[nt][1] * inv0 * (1.f / (1.f + __expf(-gv01)))));
        o1.x = __uint_as_float(f2tf(oacc[nt][2] * inv1 * (1.f / (1.f + __expf(-gv10)))));
        o1.y = __uint_as_float(f2tf(oacc[nt][3] * inv1 * (1.f / (1.f + __expf(-gv11)))));
        *(float2*)&g_att[((size_t)b * NT + tg0) * CM + h * 32 + d] = o0;
        *(float2*)&g_att[((size_t)b * NT + tg1) * CM + h * 32 + d] = o1;
    }
}

// ============================================================
// K4: out = g_att @ W0 ; tile 32x64, 128 thr, grid (128,4)
// ============================================================
__global__ void __launch_bounds__(128) out_kernel(const float* __restrict__ W0,
                                                  float* __restrict__ out) {
    __shared__ __align__(16) unsigned As[32 * 36];
    __shared__ __align__(16) unsigned Bs[32 * 72];
    const int tid = threadIdx.x;
    const int warp = tid >> 5, lane = tid & 31;
    const int g = lane >> 2, tig = lane & 3;
    const int wm = warp >> 1, wn = warp & 1;
    const int m0 = blockIdx.x * 32, n0 = blockIdx.y * 64;

    float acc[4][4];
#pragma unroll
    for (int j = 0; j < 4; j++)
#pragma unroll
        for (int c = 0; c < 4; c++) acc[j][c] = 0.f;

    for (int k0 = 0; k0 < CM; k0 += 32) {
        __syncthreads();
        {   // A: 32 rows x 32 k raw tf32 bits
#pragma unroll
            for (int p = 0; p < 2; p++) {
                int idx = tid + p * 128;
                int row = idx >> 3, c4 = (idx & 7) * 4;
                *(uint4*)(As + row * 36 + c4) =
                    *(const uint4*)(g_att + (size_t)(m0 + row) * CM + k0 + c4);
            }
        }
        {   // B: 32 rows x 64 n, RNA cvt
#pragma unroll
            for (int p = 0; p < 4; p++) {
                int idx = tid + p * 128;
                int row = idx >> 4, c4 = (idx & 15) * 4;
                float4 v = *(const float4*)(W0 + (size_t)(k0 + row) * CM + n0 + c4);
                unsigned* dst = Bs + row * 72 + c4;
                dst[0] = f2tf(v.x); dst[1] = f2tf(v.y);
                dst[2] = f2tf(v.z); dst[3] = f2tf(v.w);
            }
        }
        __syncthreads();
#pragma unroll
        for (int kc = 0; kc < 4; kc++) {
            int r = wm * 16;
            unsigned a0 = As[(r + g) * 36 + kc * 8 + tig];
            unsigned a1 = As[(r + g + 8) * 36 + kc * 8 + tig];
            unsigned a2 = As[(r + g) * 36 + kc * 8 + tig + 4];
            unsigned a3 = As[(r + g + 8) * 36 + kc * 8 + tig + 4];
#pragma unroll
            for (int nt = 0; nt < 4; nt++) {
                int c = wn * 32 + nt * 8;
                unsigned b0 = Bs[(kc * 8 + tig) * 72 + c + g];
                unsigned b1 = Bs[(kc * 8 + tig + 4) * 72 + c + g];
                mma8(acc[nt], a0, a1, a2, a3, b0, b1);
            }
        }
    }
    int m = m0 + wm * 16 + g;
#pragma unroll
    for (int nt = 0; nt < 4; nt++) {
        int n = n0 + wn * 32 + nt * 8 + 2 * tig;
        *(float2*)&out[(size_t)m * CM + n]       = make_float2(acc[nt][0], acc[nt][1]);
        *(float2*)&out[(size_t)(m + 8) * CM + n] = make_float2(acc[nt][2], acc[nt][3]);
    }
}

// ============================================================
extern "C" void kernel_launch(void* const* d_in, const int* in_sizes, int n_in,
                              void* d_out, int out_size) {
    (void)in_sizes; (void)n_in; (void)out_size;
    const float* x        = (const float*)d_in[0];
    const float* bias_rep = (const float*)d_in[1];
    const float* Wqkv     = (const float*)d_in[2];
    const float* W0       = (const float*)d_in[3];
    const float* Wb       = (const float*)d_in[4];
    const float* bb       = (const float*)d_in[5];
    float* out = (float*)d_out;

    cudaFuncSetAttribute(fused1_kernel,
                         cudaFuncAttributeMaxDynamicSharedMemorySize, FUSED_SMEM);
    cudaFuncSetAttribute(attn_kernel,
                         cudaFuncAttributeMaxDynamicSharedMemorySize, ATTN_SMEM);
    fused1_kernel<<<BIAS_BLOCKS + 512, 256, FUSED_SMEM>>>(x, Wqkv, bias_rep, Wb, bb);
    attn_kernel<<<dim3(32, 16), 128, ATTN_SMEM>>>();
    out_kernel<<<dim3(128, 4), 128>>>(W0, out);
}

// round 10
// speedup vs baseline: 1.1242x; 1.1242x over previous
#include <cuda_runtime.h>
#include <cuda_fp16.h>
#include <math.h>

#define NB 4
#define NT 1024
#define CM 256
#define NH 8
#define DHD 32
#define MTOT (NB*NT)   // 4096
#define NTSQ (NT*NT)

#define QSCALE (0.17677669529663687f * 1.4426950408889634f)
#define LOG2E  1.4426950408889634f

// ---- scratch (device globals) ----
__device__ float g_qkvT[(size_t)4*CM*MTOT];   // q tf32*QSCALE, k tf32, g fp32
__device__ __half g_vh[(size_t)CM*MTOT];      // v fp16: [(d*8+h)][m]
__device__ __half g_pbh[(size_t)NH*NT*NT];    // [h][i*1024+j], * log2e, fp16
__device__ float g_att[(size_t)MTOT*CM];      // [m][h*32+d]  tf32-bit floats

__device__ __forceinline__ unsigned f2tf(float x) {
    unsigned r; asm("cvt.rna.tf32.f32 %0, %1;" : "=r"(r) : "f"(x)); return r;
}
__device__ __forceinline__ unsigned fu(float x) { return __float_as_uint(x); }
__device__ __forceinline__ float ex2(float x) {
    float r; asm("ex2.approx.ftz.f32 %0, %1;" : "=f"(r) : "f"(x)); return r;
}
__device__ __forceinline__ void mma8(float* d, unsigned a0, unsigned a1,
                                     unsigned a2, unsigned a3,
                                     unsigned b0, unsigned b1) {
    asm("mma.sync.aligned.m16n8k8.row.col.f32.tf32.tf32.f32 "
        "{%0,%1,%2,%3}, {%4,%5,%6,%7}, {%8,%9}, {%0,%1,%2,%3};"
        : "+f"(d[0]), "+f"(d[1]), "+f"(d[2]), "+f"(d[3])
        : "r"(a0), "r"(a1), "r"(a2), "r"(a3), "r"(b0), "r"(b1));
}
__device__ __forceinline__ void mma16h(float* d, unsigned a0, unsigned a1,
                                       unsigned a2, unsigned a3,
                                       unsigned b0, unsigned b1) {
    asm("mma.sync.aligned.m16n8k16.row.col.f32.f16.f16.f32 "
        "{%0,%1,%2,%3}, {%4,%5,%6,%7}, {%8,%9}, {%0,%1,%2,%3};"
        : "+f"(d[0]), "+f"(d[1]), "+f"(d[2]), "+f"(d[3])
        : "r"(a0), "r"(a1), "r"(a2), "r"(a3), "r"(b0), "r"(b1));
}
__device__ __forceinline__ void cpa16(void* dst, const void* src) {
    unsigned s = (unsigned)__cvta_generic_to_shared(dst);
    asm volatile("cp.async.cg.shared.global [%0], [%1], 16;" :: "r"(s), "l"(src));
}
#define CP_COMMIT asm volatile("cp.async.commit_group;")
#define CP_WAIT0  asm volatile("cp.async.wait_group 0;")
#define CP_WAIT1  asm volatile("cp.async.wait_group 1;")

#define QKV_BLOCKS 512
#define FUSED_SMEM 67584
#define ATTN_SMEM  81920   // Qs 17408 + K dbuf 18432 + V dbuf 9216 + pb dbuf 36864

// ============================================================
// K1 fused: blocks [0,512) -> qkv GEMM ; blocks [512,8704) -> pair-bias
// ============================================================
__global__ void __launch_bounds__(256) fused1_kernel(const float* __restrict__ x,
                                                     const float* __restrict__ Wqkv,
                                                     const float* __restrict__ bias_rep,
                                                     const float* __restrict__ Wb,
                                                     const float* __restrict__ bb) {
    extern __shared__ __align__(16) unsigned char smem_raw[];
    const int tid = threadIdx.x;
    const int warp = tid >> 5, lane = tid & 31;
    const int g = lane >> 2, tig = lane & 3;

    if (blockIdx.x < QKV_BLOCKS) {
        // ---------------- qkv role ----------------
        float* As = (float*)smem_raw;              // [128][36]
        float* Bs = As + 128 * 36;                 // [32][72]
        float* Ts = (float*)smem_raw;              // epilogue [64][132]
        const int wm = warp >> 1, wn = warp & 1;
        const int m0 = ((int)blockIdx.x & 31) * 128;
        const int n0 = ((int)blockIdx.x >> 5) * 64;

        float acc[2][4][4];
#pragma unroll
        for (int i = 0; i < 2; i++)
#pragma unroll
            for (int j = 0; j < 4; j++)
#pragma unroll
                for (int c = 0; c < 4; c++) acc[i][j][c] = 0.f;

        for (int k0 = 0; k0 < CM; k0 += 32) {
            __syncthreads();
            {
                int row = tid >> 1, half = tid & 1;
#pragma unroll
                for (int q = 0; q < 4; q++)
                    cpa16(As + row * 36 + half * 16 + q * 4,
                          x + (size_t)(m0 + row) * CM + k0 + half * 16 + q * 4);
            }
            {
#pragma unroll
                for (int p = 0; p < 2; p++) {
                    int row = (tid >> 4) + p * 16, c4 = (tid & 15) * 4;
                    cpa16(Bs + row * 72 + c4,
                          Wqkv + (size_t)(k0 + row) * 1024 + n0 + c4);
                }
            }
            CP_COMMIT; CP_WAIT0;
            __syncthreads();
#pragma unroll
            for (int kc = 0; kc < 4; kc++) {
                unsigned a[2][4];
#pragma unroll
                for (int mt = 0; mt < 2; mt++) {
                    int r = wm * 32 + mt * 16;
                    a[mt][0] = f2tf(As[(r + g) * 36 + kc * 8 + tig]);
                    a[mt][1] = f2tf(As[(r + g + 8) * 36 + kc * 8 + tig]);
                    a[mt][2] = f2tf(As[(r + g) * 36 + kc * 8 + tig + 4]);
                    a[mt][3] = f2tf(As[(r + g + 8) * 36 + kc * 8 + tig + 4]);
                }
#pragma unroll
                for (int nt = 0; nt < 4; nt++) {
                    int c = wn * 32 + nt * 8;
                    unsigned b0 = f2tf(Bs[(kc * 8 + tig) * 72 + c + g]);
                    unsigned b1 = f2tf(Bs[(kc * 8 + tig + 4) * 72 + c + g]);
                    mma8(acc[0][nt], a[0][0], a[0][1], a[0][2], a[0][3], b0, b1);
                    mma8(acc[1][nt], a[1][0], a[1][1], a[1][2], a[1][3], b0, b1);
                }
            }
        }
        __syncthreads();
#pragma unroll
        for (int mt = 0; mt < 2; mt++) {
            int r = wm * 32 + mt * 16 + g;
#pragma unroll
            for (int nt = 0; nt < 4; nt++) {
                int c = wn * 32 + nt * 8 + 2 * tig;
                Ts[c * 132 + r]           = acc[mt][nt][0];
                Ts[(c + 1) * 132 + r]     = acc[mt][nt][1];
                Ts[c * 132 + r + 8]       = acc[mt][nt][2];
                Ts[(c + 1) * 132 + r + 8] = acc[mt][nt][3];
            }
        }
        __syncthreads();
        {
            int col = tid >> 2, q = tid & 3;
            int n = n0 + col;
            int d = n >> 5, rr = n & 31;
            int kk = rr >> 3, h = rr & 7;
            const float* srcT = Ts + col * 132 + q * 32;
            if (kk == 2) {
                __half* dst = g_vh + (size_t)(d * 8 + h) * MTOT + m0 + q * 32;
#pragma unroll
                for (int i = 0; i < 4; i++) {
                    float4 v0 = *(const float4*)(srcT + i * 8);
                    float4 v1 = *(const float4*)(srcT + i * 8 + 4);
                    __half2 h0 = __floats2half2_rn(v0.x, v0.y);
                    __half2 h1 = __floats2half2_rn(v0.z, v0.w);
                    __half2 h2 = __floats2half2_rn(v1.x, v1.y);
                    __half2 h3 = __floats2half2_rn(v1.z, v1.w);
                    uint4 o = make_uint4(*(unsigned*)&h0, *(unsigned*)&h1,
                                         *(unsigned*)&h2, *(unsigned*)&h3);
                    *(uint4*)(dst + i * 8) = o;
                }
            } else {
                float* dst = g_qkvT + (size_t)n * MTOT + m0 + q * 32;
                if (kk == 3) {
#pragma unroll
                    for (int i = 0; i < 8; i++)
                        *(float4*)(dst + i * 4) = *(const float4*)(srcT + i * 4);
                } else {
                    float sc = (kk == 0) ? QSCALE : 1.0f;
#pragma unroll
                    for (int i = 0; i < 8; i++) {
                        float4 v = *(const float4*)(srcT + i * 4);
                        float4 o;
                        o.x = __uint_as_float(f2tf(v.x * sc));
                        o.y = __uint_as_float(f2tf(v.y * sc));
                        o.z = __uint_as_float(f2tf(v.z * sc));
                        o.w = __uint_as_float(f2tf(v.w * sc));
                        *(float4*)(dst + i * 4) = o;
                    }
                }
            }
        }
    } else {
        // ---------------- bias role: per-warp pipelined; cpa issued FIRST ----------------
        float* As = (float*)smem_raw + warp * (16 * 132);
        const int bid = (int)blockIdx.x - QKV_BLOCKS;   // 0..8191
        const int bi = bid >> 3;
        const int j0 = (bid & 7) * 128 + warp * 16;

        const float* src = bias_rep + ((size_t)bi * NT + j0) * 128;
        // group A: columns [0,64) — issue before anything else
#pragma unroll
        for (int p = 0; p < 8; p++) {
            int idx = lane + p * 32;
            int row = idx >> 4, c4 = (idx & 15) * 4;
            cpa16(As + row * 132 + c4, src + (size_t)row * 128 + c4);
        }
        CP_COMMIT;
        // group B: columns [64,128)
#pragma unroll
        for (int p = 0; p < 8; p++) {
            int idx = lane + p * 32;
            int row = idx >> 4, c4 = (idx & 15) * 4 + 64;
            cpa16(As + row * 132 + c4, src + (size_t)row * 128 + c4);
        }
        CP_COMMIT;

        // weights (L2-hot) load under the cp.async stream
        unsigned wb0[16], wb1[16];
#pragma unroll
        for (int kc = 0; kc < 16; kc++) {
            wb0[kc] = f2tf(__ldg(&Wb[(kc * 8 + tig) * 8 + g]));
            wb1[kc] = f2tf(__ldg(&Wb[(kc * 8 + tig + 4) * 8 + g]));
        }
        float bbv0 = __ldg(&bb[2 * tig]);
        float bbv1 = __ldg(&bb[2 * tig + 1]);

        float dd[4] = {0.f, 0.f, 0.f, 0.f};
        CP_WAIT1;  __syncwarp();
#pragma unroll
        for (int kc = 0; kc < 8; kc++) {
            unsigned a0 = f2tf(As[g * 132 + kc * 8 + tig]);
            unsigned a1 = f2tf(As[(g + 8) * 132 + kc * 8 + tig]);
            unsigned a2 = f2tf(As[g * 132 + kc * 8 + tig + 4]);
            unsigned a3 = f2tf(As[(g + 8) * 132 + kc * 8 + tig + 4]);
            mma8(dd, a0, a1, a2, a3, wb0[kc], wb1[kc]);
        }
        CP_WAIT0;  __syncwarp();
#pragma unroll
        for (int kc = 8; kc < 16; kc++) {
            unsigned a0 = f2tf(As[g * 132 + kc * 8 + tig]);
            unsigned a1 = f2tf(As[(g + 8) * 132 + kc * 8 + tig]);
            unsigned a2 = f2tf(As[g * 132 + kc * 8 + tig + 4]);
            unsigned a3 = f2tf(As[(g + 8) * 132 + kc * 8 + tig + 4]);
            mma8(dd, a0, a1, a2, a3, wb0[kc], wb1[kc]);
        }
        size_t m = (size_t)bi * NT + j0 + g;
        g_pbh[(size_t)(2 * tig) * NTSQ     + m]     = __float2half((dd[0] + bbv0) * LOG2E);
        g_pbh[(size_t)(2 * tig + 1) * NTSQ + m]     = __float2half((dd[1] + bbv1) * LOG2E);
        g_pbh[(size_t)(2 * tig) * NTSQ     + m + 8] = __float2half((dd[2] + bbv0) * LOG2E);
        g_pbh[(size_t)(2 * tig + 1) * NTSQ + m + 8] = __float2half((dd[3] + bbv1) * LOG2E);
    }
}

// ============================================================
// K3: flash attention; S: tf32 HMMA; PV: fp16 HMMA
// 256 thr = 8 warps; block = (b,h) x 128 q-rows
// K/V/pb all double-buffered via cp.async (pb smem: coalesced + prefetched)
// ============================================================
__global__ void __launch_bounds__(256, 2) attn_kernel() {
    extern __shared__ float asmem[];
    float* Qs = asmem;                          // [32][136] fp32
    float* Ksb0 = asmem + 4352;                 // [32][72] fp32
    float* Ksb1 = asmem + 6656;
    __half* Vsb0 = (__half*)(asmem + 8960);     // [32][72] half
    __half* Vsb1 = (__half*)(asmem + 10112);
    __half* Pbs0 = (__half*)(asmem + 11264);    // [128][72] half
    __half* Pbs1 = (__half*)(asmem + 15872);

    const int bh = blockIdx.x;
    const int b = bh >> 3, h = bh & 7;
    const int i0 = blockIdx.y * 128;
    const int tid = threadIdx.x;
    const int w = tid >> 5, lane = tid & 31;
    const int g = lane >> 2, tig = lane & 3;

    const __half* pbsrc = g_pbh + (size_t)h * NTSQ + (size_t)i0 * NT;

    // stage Q (once)
#pragma unroll
    for (int r = 0; r < 4; r++) {
        int c = tid + r * 256;
        int d = c >> 5, c4 = (c & 31) * 4;
        cpa16(Qs + d * 136 + c4,
              g_qkvT + (size_t)(d * 32 + h) * MTOT + b * NT + i0 + c4);
    }
    // stage K/V/pb tile 0
#pragma unroll
    for (int r = 0; r < 2; r++) {
        int c = tid + r * 256;
        int d = c >> 4, c4 = (c & 15) * 4;
        cpa16(Ksb0 + d * 72 + c4, g_qkvT + (size_t)(d * 32 + 8 + h) * MTOT + b * NT + c4);
    }
    {
        int d = tid >> 3, c8 = (tid & 7) * 8;
        cpa16(Vsb0 + d * 72 + c8, g_vh + (size_t)(d * 8 + h) * MTOT + b * NT + c8);
    }
#pragma unroll
    for (int r = 0; r < 4; r++) {
        int c = tid + r * 256;
        int row = c >> 3, c8 = (c & 7) * 8;
        cpa16(Pbs0 + row * 72 + c8, pbsrc + (size_t)row * NT + c8);
    }
    CP_COMMIT;

    float oacc[4][4];
#pragma unroll
    for (int i = 0; i < 4; i++)
#pragma unroll
        for (int c = 0; c < 4; c++) oacc[i][c] = 0.f;
    float mrow0 = -1e30f, mrow1 = -1e30f, lsum0 = 0.f, lsum1 = 0.f;

    for (int n = 0; n < 16; n++) {
        CP_WAIT0;
        __syncthreads();
        const float* Ks = (n & 1) ? Ksb1 : Ksb0;
        const __half* Vs = (n & 1) ? Vsb1 : Vsb0;
        const __half* Pb = (n & 1) ? Pbs1 : Pbs0;
        if (n < 15) {
            float* Kd = (n & 1) ? Ksb0 : Ksb1;
            __half* Vd = (n & 1) ? Vsb0 : Vsb1;
            __half* Pd = (n & 1) ? Pbs0 : Pbs1;
            int jn = (n + 1) * 64;
#pragma unroll
            for (int r = 0; r < 2; r++) {
                int c = tid + r * 256;
                int d = c >> 4, c4 = (c & 15) * 4;
                cpa16(Kd + d * 72 + c4,
                      g_qkvT + (size_t)(d * 32 + 8 + h) * MTOT + b * NT + jn + c4);
            }
            {
                int d = tid >> 3, c8 = (tid & 7) * 8;
                cpa16(Vd + d * 72 + c8,
                      g_vh + (size_t)(d * 8 + h) * MTOT + b * NT + jn + c8);
            }
#pragma unroll
            for (int r = 0; r < 4; r++) {
                int c = tid + r * 256;
                int row = c >> 3, c8 = (c & 7) * 8;
                cpa16(Pd + row * 72 + c8, pbsrc + (size_t)row * NT + jn + c8);
            }
            CP_COMMIT;
        }

        // S = Q K^T (tf32)
        float sa[8][4];
#pragma unroll
        for (int nt = 0; nt < 8; nt++)
#pragma unroll
            for (int c = 0; c < 4; c++) sa[nt][c] = 0.f;
#pragma unroll
        for (int kc = 0; kc < 4; kc++) {
            const float* qrow = Qs + (kc * 8 + tig) * 136 + w * 16 + g;
            unsigned a0 = fu(qrow[0]);
            unsigned a1 = fu(qrow[8]);
            unsigned a2 = fu(qrow[544]);
            unsigned a3 = fu(qrow[552]);
#pragma unroll
            for (int nt = 0; nt < 8; nt++) {
                unsigned b0 = fu(Ks[(kc * 8 + tig) * 72 + nt * 8 + g]);
                unsigned b1 = fu(Ks[(kc * 8 + tig + 4) * 72 + nt * 8 + g]);
                mma8(sa[nt], a0, a1, a2, a3, b0, b1);
            }
        }
        // + pair bias (from smem, conflict-free half2)
#pragma unroll
        for (int nt = 0; nt < 8; nt++) {
            float2 p0 = __half22float2(*(const __half2*)&Pb[(w * 16 + g) * 72 + nt * 8 + 2 * tig]);
            float2 p1 = __half22float2(*(const __half2*)&Pb[(w * 16 + g + 8) * 72 + nt * 8 + 2 * tig]);
            sa[nt][0] += p0.x; sa[nt][1] += p0.y;
            sa[nt][2] += p1.x; sa[nt][3] += p1.y;
        }
        // online softmax (exp2)
        float t0 = -1e30f, t1 = -1e30f;
#pragma unroll
        for (int nt = 0; nt < 8; nt++) {
            t0 = fmaxf(t0, fmaxf(sa[nt][0], sa[nt][1]));
            t1 = fmaxf(t1, fmaxf(sa[nt][2], sa[nt][3]));
        }
        t0 = fmaxf(t0, __shfl_xor_sync(0xffffffffu, t0, 1));
        t0 = fmaxf(t0, __shfl_xor_sync(0xffffffffu, t0, 2));
        t1 = fmaxf(t1, __shfl_xor_sync(0xffffffffu, t1, 1));
        t1 = fmaxf(t1, __shfl_xor_sync(0xffffffffu, t1, 2));
        float mn0 = fmaxf(mrow0, t0), mn1 = fmaxf(mrow1, t1);
        float corr0 = ex2(mrow0 - mn0), corr1 = ex2(mrow1 - mn1);
        mrow0 = mn0; mrow1 = mn1;
        float l0 = 0.f, l1 = 0.f;
#pragma unroll
        for (int nt = 0; nt < 8; nt++) {
            sa[nt][0] = ex2(sa[nt][0] - mn0); l0 += sa[nt][0];
            sa[nt][1] = ex2(sa[nt][1] - mn0); l0 += sa[nt][1];
            sa[nt][2] = ex2(sa[nt][2] - mn1); l1 += sa[nt][2];
            sa[nt][3] = ex2(sa[nt][3] - mn1); l1 += sa[nt][3];
        }
        l0 += __shfl_xor_sync(0xffffffffu, l0, 1);
        l0 += __shfl_xor_sync(0xffffffffu, l0, 2);
        l1 += __shfl_xor_sync(0xffffffffu, l1, 1);
        l1 += __shfl_xor_sync(0xffffffffu, l1, 2);
        lsum0 = lsum0 * corr0 + l0;
        lsum1 = lsum1 * corr1 + l1;
#pragma unroll
        for (int nt = 0; nt < 4; nt++) {
            oacc[nt][0] *= corr0; oacc[nt][1] *= corr0;
            oacc[nt][2] *= corr1; oacc[nt][3] *= corr1;
        }

        // O += P @ V (fp16 mma, P C-frag == A-frag)
#pragma unroll
        for (int kc = 0; kc < 4; kc++) {
            __half2 h0 = __floats2half2_rn(sa[2 * kc][0],     sa[2 * kc][1]);
            __half2 h1 = __floats2half2_rn(sa[2 * kc][2],     sa[2 * kc][3]);
            __half2 h2 = __floats2half2_rn(sa[2 * kc + 1][0], sa[2 * kc + 1][1]);
            __half2 h3 = __floats2half2_rn(sa[2 * kc + 1][2], sa[2 * kc + 1][3]);
            unsigned a0 = *(unsigned*)&h0, a1 = *(unsigned*)&h1;
            unsigned a2 = *(unsigned*)&h2, a3 = *(unsigned*)&h3;
#pragma unroll
            for (int nt = 0; nt < 4; nt++) {
                unsigned b0 = *(const unsigned*)&Vs[(nt * 8 + g) * 72 + kc * 16 + 2 * tig];
                unsigned b1 = *(const unsigned*)&Vs[(nt * 8 + g) * 72 + kc * 16 + 2 * tig + 8];
                mma16h(oacc[nt], a0, a1, a2, a3, b0, b1);
            }
        }
        pbsrc += 64;   // advance j inside the row via jn; base stays per-row
        pbsrc -= 64;   // (jn used explicitly; keep base fixed)
    }

    // epilogue
    float inv0 = 1.f / lsum0, inv1 = 1.f / lsum1;
    int tg0 = i0 + w * 16 + g, tg1 = tg0 + 8;
#pragma unroll
    for (int nt = 0; nt < 4; nt++) {
        int d = nt * 8 + 2 * tig;
        const float* gq0 = g_qkvT + (size_t)(d * 32 + 24 + h) * MTOT + b * NT;
        const float* gq1 = g_qkvT + (size_t)((d + 1) * 32 + 24 + h) * MTOT + b * NT;
        float gv00 = gq0[tg0], gv01 = gq1[tg0];
        float gv10 = gq0[tg1], gv11 = gq1[tg1];
        float2 o0, o1;
        o0.x = __uint_as_float(f2tf(oacc[nt][0] * inv0 * (1.f / (1.f + __expf(-gv00)))));
        o0.y = __uint_as_float(f2tf(oacc[nt][1] * inv0 * (1.f / (1.f + __expf(-gv01)))));
        o1.x = __uint_as_float(f2tf(oacc[nt][2] * inv1 * (1.f / (1.f + __expf(-gv10)))));
        o1.y = __uint_as_float(f2tf(oacc[nt][3] * inv1 * (1.f / (1.f + __expf(-gv11)))));
        *(float2*)&g_att[((size_t)b * NT + tg0) * CM + h * 32 + d] = o0;
        *(float2*)&g_att[((size_t)b * NT + tg1) * CM + h * 32 + d] = o1;
    }
}

// ============================================================
// K4: out = g_att @ W0  (M=4096,K=256,N=256), 64x64 tile
// ============================================================
__global__ void __launch_bounds__(256) out_kernel(const float* __restrict__ W0,
                                                  float* __restrict__ out) {
    __shared__ __align__(16) unsigned As[64 * 36];
    __shared__ __align__(16) unsigned Bs[32 * 72];
    const int tid = threadIdx.x;
    const int warp = tid >> 5, lane = tid & 31;
    const int g = lane >> 2, tig = lane & 3;
    const int wm = warp >> 2, wn = warp & 3;
    const int m0 = blockIdx.x * 64, n0 = blockIdx.y * 64;

    float acc[2][2][4];
#pragma unroll
    for (int i = 0; i < 2; i++)
#pragma unroll
        for (int j = 0; j < 2; j++)
#pragma unroll
            for (int c = 0; c < 4; c++) acc[i][j][c] = 0.f;

    for (int k0 = 0; k0 < CM; k0 += 32) {
        __syncthreads();
        {
#pragma unroll
            for (int p = 0; p < 2; p++) {
                int idx = tid + p * 256;
                int row = idx >> 3, c4 = (idx & 7) * 4;
                *(uint4*)(As + row * 36 + c4) =
                    *(const uint4*)(g_att + (size_t)(m0 + row) * CM + k0 + c4);
            }
        }
        {
#pragma unroll
            for (int p = 0; p < 2; p++) {
                int idx = tid + p * 256;
                int row = idx >> 4, c4 = (idx & 15) * 4;
                float4 v = *(const float4*)(W0 + (size_t)(k0 + row) * CM + n0 + c4);
                unsigned* dst = Bs + row * 72 + c4;
                dst[0] = f2tf(v.x); dst[1] = f2tf(v.y);
                dst[2] = f2tf(v.z); dst[3] = f2tf(v.w);
            }
        }
        __syncthreads();
#pragma unroll
        for (int kc = 0; kc < 4; kc++) {
            unsigned a[2][4];
#pragma unroll
            for (int mt = 0; mt < 2; mt++) {
                int r = wm * 32 + mt * 16;
                a[mt][0] = As[(r + g) * 36 + kc * 8 + tig];
                a[mt][1] = As[(r + g + 8) * 36 + kc * 8 + tig];
                a[mt][2] = As[(r + g) * 36 + kc * 8 + tig + 4];
                a[mt][3] = As[(r + g + 8) * 36 + kc * 8 + tig + 4];
            }
#pragma unroll
            for (int nt = 0; nt < 2; nt++) {
                int c = wn * 16 + nt * 8;
                unsigned b0 = Bs[(kc * 8 + tig) * 72 + c + g];
                unsigned b1 = Bs[(kc * 8 + tig + 4) * 72 + c + g];
                mma8(acc[0][nt], a[0][0], a[0][1], a[0][2], a[0][3], b0, b1);
                mma8(acc[1][nt], a[1][0], a[1][1], a[1][2], a[1][3], b0, b1);
            }
        }
    }
#pragma unroll
    for (int mt = 0; mt < 2; mt++) {
        int m = m0 + wm * 32 + mt * 16 + g;
#pragma unroll
        for (int nt = 0; nt < 2; nt++) {
            int n = n0 + wn * 16 + nt * 8 + 2 * tig;
            *(float2*)&out[(size_t)m * CM + n]       = make_float2(acc[mt][nt][0], acc[mt][nt][1]);
            *(float2*)&out[(size_t)(m + 8) * CM + n] = make_float2(acc[mt][nt][2], acc[mt][nt][3]);
        }
    }
}

// ============================================================
extern "C" void kernel_launch(void* const* d_in, const int* in_sizes, int n_in,
                              void* d_out, int out_size) {
    (void)in_sizes; (void)n_in; (void)out_size;
    const float* x        = (const float*)d_in[0];
    const float* bias_rep = (const float*)d_in[1];
    const float* Wqkv     = (const float*)d_in[2];
    const float* W0       = (const float*)d_in[3];
    const float* Wb       = (const float*)d_in[4];
    const float* bb       = (const float*)d_in[5];
    float* out = (float*)d_out;

    cudaFuncSetAttribute(fused1_kernel,
                         cudaFuncAttributeMaxDynamicSharedMemorySize, FUSED_SMEM);
    cudaFuncSetAttribute(attn_kernel,
                         cudaFuncAttributeMaxDynamicSharedMemorySize, ATTN_SMEM);
    fused1_kernel<<<QKV_BLOCKS + 8192, 256, FUSED_SMEM>>>(x, Wqkv, bias_rep, Wb, bb);
    attn_kernel<<<dim3(32, 8), 256, ATTN_SMEM>>>();
    out_kernel<<<dim3(64, 4), 256>>>(W0, out);
}